// round 7
// baseline (speedup 1.0000x reference)
#include <cuda_runtime.h>
#include <math.h>

#define NN 8192
#define CH 32
#define NP (NN / 16)   // packed u32 words per adj row

// ---------------- device scratch (no allocation allowed) ----------------
__device__ __align__(256) unsigned g_A[(long)NN * NP];          // 2-bit packed adj (16 MB)
__device__ __align__(256) unsigned char g_H8T[3L * CH * NN];    // s8 H, [plane][c][j] (768 KB)
__device__ __align__(256) float g_Hf[3L * NN * CH];             // fp32 H, [plane][j][c] (3 MB)
__device__ __align__(256) int   g_P[8L * NN * CH];              // k-split s32 partials (8 MB)
__device__ float    g_pool[256 * CH];
__device__ unsigned g_maxbits[2][CH];                           // per-column |H| max (fp32 bits)

// ---------------------------------------------------------------------------
__global__ void init_kernel() {
    ((unsigned*)g_maxbits)[threadIdx.x] = 0u;   // 64 threads
}

// ---------------------------------------------------------------------------
// hgen: build fp32 H planes for a layer + per-column max.
// layer 0: Z = V.  layer 1: Z = relu(gb0 + scale0_c * sum_s P[s]).
// grid 256 x 256 threads (32 rows/block, warp = 4 rows).
// ---------------------------------------------------------------------------
__global__ __launch_bounds__(256) void hgen_kernel(const float* __restrict__ V,
                                                   const float* __restrict__ bias,
                                                   const float* __restrict__ w1,
                                                   const float* __restrict__ w2,
                                                   const float* __restrict__ w3,
                                                   int layer) {
    __shared__ float sw[3][32][32];
    __shared__ float sZ[32][33];
    __shared__ float sred[8][32];
    const int tid = threadIdx.x;
#pragma unroll
    for (int qq = 0; qq < 4; qq++) {
        int id = tid + qq * 256;
        sw[0][id >> 5][id & 31] = w1[id];
        sw[1][id >> 5][id & 31] = w2[id];
        sw[2][id >> 5][id & 31] = w3[id];
    }
    const int c = tid & 31, w = tid >> 5;
    const int j0 = blockIdx.x * 32;
    float scale = 0.f;
    if (layer) scale = __uint_as_float(g_maxbits[0][c]) * (1.f / 127.f);
#pragma unroll
    for (int rr = 0; rr < 4; rr++) {
        const int lr = w * 4 + rr, row = j0 + lr;
        float z;
        if (!layer) {
            z = V[(long)row * CH + c];
        } else {
            int s = 0;
#pragma unroll
            for (int p = 0; p < 8; p++) s += g_P[((long)p * NN + row) * CH + c];
            z = fmaxf(bias[c] + scale * (float)s, 0.f);
        }
        sZ[lr][c] = z;
    }
    __syncthreads();
    float m = 0.f;
#pragma unroll
    for (int rr = 0; rr < 4; rr++) {
        const int lr = w * 4 + rr;
        float a0 = 0.f, a1 = 0.f, a2 = 0.f;
#pragma unroll
        for (int d = 0; d < 32; d++) {
            float zd = sZ[lr][d];
            a0 += zd * sw[0][d][c];
            a1 += zd * sw[1][d][c];
            a2 += zd * sw[2][d][c];
        }
        const long jr = j0 + lr;
        g_Hf[(0L * NN + jr) * CH + c] = a0;
        g_Hf[(1L * NN + jr) * CH + c] = a1;
        g_Hf[(2L * NN + jr) * CH + c] = a2;
        m = fmaxf(m, fmaxf(fabsf(a0), fmaxf(fabsf(a1), fabsf(a2))));
    }
    sred[w][c] = m;
    __syncthreads();
    if (w == 0) {
        float mm = sred[0][c];
#pragma unroll
        for (int qq = 1; qq < 8; qq++) mm = fmaxf(mm, sred[qq][c]);
        atomicMax(&g_maxbits[layer][c], __float_as_uint(mm));
    }
}

// ---------------------------------------------------------------------------
// quant: g_Hf -> s8 g_H8T (transposed [plane][c][j]) using per-column scales.
// grid 256 x 256 (32 j per block), smem transpose.
// ---------------------------------------------------------------------------
__global__ __launch_bounds__(256) void quant_kernel(int layer) {
    __shared__ unsigned char sT[3][32][36];
    __shared__ float sinv[32];
    const int tid = threadIdx.x;
    if (tid < 32) {
        float mx = __uint_as_float(g_maxbits[layer][tid]);
        sinv[tid] = (mx > 0.f) ? (127.f / mx) : 0.f;
    }
    __syncthreads();
    const int j0 = blockIdx.x * 32;
#pragma unroll
    for (int k = 0; k < 12; k++) {
        int id = tid + k * 256;                 // (plane, r, c)
        int plane = id >> 10, rem = id & 1023;
        int r = rem >> 5, c = rem & 31;
        float h = g_Hf[((long)plane * NN + j0 + r) * CH + c];
        int q = __float2int_rn(h * sinv[c]);
        sT[plane][c][r] = (unsigned char)q;
    }
    __syncthreads();
#pragma unroll
    for (int k = 0; k < 3; k++) {
        int id = tid + k * 256;                 // (plane, c, word)
        int plane = id >> 8, rem = id & 255;
        int c = rem >> 3, wd = rem & 7;
        unsigned v = *(const unsigned*)&sT[plane][c][wd * 4];
        *(unsigned*)&g_H8T[((long)plane * CH + c) * NN + j0 + wd * 4] = v;
    }
}

// ---------------------------------------------------------------------------
// gcn: masked matmul via int8 IMMA m16n8k32. grid (64 m-tiles, 8 k-splits).
// LAYER 0: reads raw adj, also writes 2-bit packed g_A.  LAYER 1: reads g_A.
// ---------------------------------------------------------------------------
__device__ __forceinline__ void mma_s8(int* c, const unsigned* a, unsigned b0, unsigned b1) {
    asm volatile(
        "mma.sync.aligned.m16n8k32.row.col.s32.s8.s8.s32 "
        "{%0,%1,%2,%3},{%4,%5,%6,%7},{%8,%9},{%0,%1,%2,%3};"
        : "+r"(c[0]), "+r"(c[1]), "+r"(c[2]), "+r"(c[3])
        : "r"(a[0]), "r"(a[1]), "r"(a[2]), "r"(a[3]), "r"(b0), "r"(b1));
}

__device__ __forceinline__ void selpack(int4 a, unsigned& sel, unsigned& pb) {
    unsigned t0 = a.x & 3, t1 = a.y & 3, t2 = a.z & 3, t3 = a.w & 3;
    sel = t0 | (t1 << 4) | (t2 << 8) | (t3 << 12);
    pb  = t0 | (t1 << 2) | (t2 << 4) | (t3 << 6);
}

template <int LAYER>
__global__ __launch_bounds__(256) void gcn_kernel(const int* __restrict__ adj) {
    __shared__ __align__(16) unsigned char sHT[3 * 32 * 144];  // row stride 144B (36 words)
    __shared__ unsigned slut[256];

    const int tid = threadIdx.x;
    if (LAYER == 1) {
        unsigned b = (unsigned)tid;
        slut[tid] = (b & 3) | (((b >> 2) & 3) << 4) | (((b >> 4) & 3) << 8) | (((b >> 6) & 3) << 12);
    }
    const int warp = tid >> 5, lane = tid & 31;
    const int g = lane >> 2, q = lane & 3;
    const int i0 = blockIdx.x * 128;
    const int ksp = blockIdx.y;
    const long jbase = (long)ksp * 1024;
    const int rg = i0 + warp * 16 + g;

    int acc[16];
#pragma unroll
    for (int x = 0; x < 16; x++) acc[x] = 0;

    // quad-transpose invariants (pack path)
    const unsigned sel_u = q | ((4 + q) << 4);
    const unsigned sel_f = (1u << (4 * (q ^ 1))) | (4u << (4 * (q ^ 2))) | (5u << (4 * (q ^ 3)));

    for (int jsb = 0; jsb < 1024; jsb += 128) {
        __syncthreads();
        // stage H^T superblock: 96 rows x 128 B (dst stride 144)
#pragma unroll
        for (int k = 0; k < 3; k++) {
            int id = tid + k * 256;
            int prow = id >> 3, wd = id & 7;
            const unsigned char* src = g_H8T + (long)prow * NN + jbase + jsb + wd * 16;
            *(uint4*)&sHT[prow * 144 + wd * 16] = *(const uint4*)src;
        }
        __syncthreads();

#pragma unroll
        for (int jo = 0; jo < 128; jo += 32) {
            unsigned s0, s1, s2, s3;
            if (LAYER == 0) {
                const int* b0p = adj + (long)rg * NN + (jbase + jsb + jo);
                const int* b1p = b0p + 8L * NN;
                int4 A0 = *(const int4*)(b0p + 4 * q);
                int4 A1 = *(const int4*)(b1p + 4 * q);
                int4 A2 = *(const int4*)(b0p + 16 + 4 * q);
                int4 A3 = *(const int4*)(b1p + 16 + 4 * q);
                unsigned p0, p1, p2, p3;
                selpack(A0, s0, p0); selpack(A1, s1, p1);
                selpack(A2, s2, p2); selpack(A3, s3, p3);
                // pack 2-bit words for gcn2: 4x4 byte transpose across the quad
                unsigned Bt = p0 | (p1 << 8) | (p2 << 16) | (p3 << 24);
                unsigned y1 = __shfl_xor_sync(0xffffffffu, Bt, 1);
                unsigned y2 = __shfl_xor_sync(0xffffffffu, Bt, 2);
                unsigned y3 = __shfl_xor_sync(0xffffffffu, Bt, 3);
                unsigned u = __byte_perm(Bt, y1, sel_u);
                unsigned v = __byte_perm(y2, y3, sel_u);
                unsigned W = __byte_perm(u, v, sel_f);
                g_A[(long)(rg + (q & 1) * 8) * NP + ((jbase + jsb + jo) >> 4) + (q >> 1)] = W;
            } else {
                const unsigned* ap = g_A + (long)rg * NP + ((jbase + jsb + jo) >> 4);
                uint2 wg = *(const uint2*)ap;
                uint2 wh = *(const uint2*)(ap + 8L * NP);
                s0 = slut[(wg.x >> (8 * q)) & 0xFF];
                s1 = slut[(wh.x >> (8 * q)) & 0xFF];
                s2 = slut[(wg.y >> (8 * q)) & 0xFF];
                s3 = slut[(wh.y >> (8 * q)) & 0xFF];
            }
#pragma unroll
            for (int m = 0; m < 3; m++) {
                const unsigned SRC = 0x100u << (8 * m);   // byte (m+1) = 0x01
                unsigned A[4] = { __byte_perm(SRC, 0, s0), __byte_perm(SRC, 0, s1),
                                  __byte_perm(SRC, 0, s2), __byte_perm(SRC, 0, s3) };
#pragma unroll
                for (int nt = 0; nt < 4; nt++) {
                    const unsigned char* hb =
                        sHT + ((m * 32 + nt * 8 + g) * 36 + (jo >> 2) + q) * 4;
                    unsigned b0 = *(const unsigned*)hb;
                    unsigned b1 = *(const unsigned*)(hb + 16);
                    mma_s8(acc + nt * 4, A, b0, b1);
                }
            }
        }
    }

    int* P = g_P + ((long)ksp * NN + i0 + warp * 16) * CH;
#pragma unroll
    for (int nt = 0; nt < 4; nt++) {
        int cix = nt * 8 + 2 * q;
        *(int2*)(P + (g)     * CH + cix) = make_int2(acc[nt * 4 + 0], acc[nt * 4 + 1]);
        *(int2*)(P + (g + 8) * CH + cix) = make_int2(acc[nt * 4 + 2], acc[nt * 4 + 3]);
    }
}

// ---------------------------------------------------------------------------
// finish2: pooled sums of relu(gb1 + scale1_c * sum_s P[s]). grid 256 x 256.
// ---------------------------------------------------------------------------
__global__ __launch_bounds__(256) void finish2_kernel(const float* __restrict__ bias) {
    __shared__ float sred[8][32];
    const int c = threadIdx.x & 31, w = threadIdx.x >> 5;
    const int j0 = blockIdx.x * 32;
    const float scale = __uint_as_float(g_maxbits[1][c]) * (1.f / 127.f);
    const float b = bias[c];
    float local = 0.f;
#pragma unroll
    for (int rr = 0; rr < 4; rr++) {
        const int row = j0 + w * 4 + rr;
        int s = 0;
#pragma unroll
        for (int p = 0; p < 8; p++) s += g_P[((long)p * NN + row) * CH + c];
        local += fmaxf(b + scale * (float)s, 0.f);
    }
    sred[w][c] = local;
    __syncthreads();
    if (w == 0) {
        float t = sred[0][c];
#pragma unroll
        for (int qq = 1; qq < 8; qq++) t += sred[qq][c];
        g_pool[blockIdx.x * 32 + c] = t;
    }
}

// ---------------------------------------------------------------------------
// final: pool -> fc0(relu) -> fc1 -> sigmoid. 1 block, 256 threads.
// ---------------------------------------------------------------------------
__global__ void final_kernel(const float* __restrict__ fcW0, const float* __restrict__ fcb0,
                             const float* __restrict__ fcW1, const float* __restrict__ fcb1,
                             float* __restrict__ out) {
    __shared__ float sred[8][32];
    __shared__ float pool[32];
    const int c = threadIdx.x & 31, w = threadIdx.x >> 5;
    float s = 0.f;
    for (int i = 0; i < 32; i++) s += g_pool[(w * 32 + i) * 32 + c];
    sred[w][c] = s;
    __syncthreads();
    if (w == 0) {
        float p = sred[0][c];
#pragma unroll
        for (int qq = 1; qq < 8; qq++) p += sred[qq][c];
        pool[c] = p;
        __syncwarp();
        float o = fcb0[c];
#pragma unroll
        for (int d = 0; d < 32; d++) o += pool[d] * fcW0[c * 32 + d];
        o = fmaxf(o, 0.f);
        float v = o * fcW1[c];
#pragma unroll
        for (int off = 16; off; off >>= 1) v += __shfl_xor_sync(0xffffffffu, v, off);
        if (c == 0) out[0] = 1.f / (1.f + expf(-(v + fcb1[0])));
    }
}

// ---------------------------------------------------------------------------
extern "C" void kernel_launch(void* const* d_in, const int* in_sizes, int n_in,
                              void* d_out, int out_size) {
    (void)in_sizes; (void)n_in; (void)out_size;
    const float* V    = (const float*)d_in[0];
    const int*   adj  = (const int*)d_in[1];
    const float* w1_0 = (const float*)d_in[2];
    const float* w2_0 = (const float*)d_in[3];
    const float* w3_0 = (const float*)d_in[4];
    const float* gb_0 = (const float*)d_in[5];
    const float* w1_1 = (const float*)d_in[6];
    const float* w2_1 = (const float*)d_in[7];
    const float* w3_1 = (const float*)d_in[8];
    const float* gb_1 = (const float*)d_in[9];
    const float* fcW0 = (const float*)d_in[10];
    const float* fcb0 = (const float*)d_in[11];
    const float* fcW1 = (const float*)d_in[12];
    const float* fcb1 = (const float*)d_in[13];

    dim3 gG(64, 8);

    init_kernel<<<1, 64>>>();                                  // zero max accumulators
    hgen_kernel<<<256, 256>>>(V, gb_0, w1_0, w2_0, w3_0, 0);   // H1 fp32 + col max
    quant_kernel<<<256, 256>>>(0);                             // H1 -> s8 transposed
    gcn_kernel<0><<<gG, 256>>>(adj);                           // layer-1 IMMA + pack adj
    hgen_kernel<<<256, 256>>>(V, gb_0, w1_1, w2_1, w3_1, 1);   // Z=relu(..), H2 fp32 + max
    quant_kernel<<<256, 256>>>(1);                             // H2 -> s8 transposed
    gcn_kernel<1><<<gG, 256>>>(adj);                           // layer-2 IMMA (packed adj)
    finish2_kernel<<<256, 256>>>(gb_1);                        // relu+bias+pool partials
    final_kernel<<<1, 256>>>(fcW0, fcb0, fcW1, fcb1, (float*)d_out);
}

// round 9
// speedup vs baseline: 1.5933x; 1.5933x over previous
#include <cuda_runtime.h>
#include <cuda_bf16.h>
#include <math.h>

// Problem constants
#define NN 8192
#define CH 32
#define NP (NN / 16)    // packed u32 words per adj row
#define KSP 16          // j-splits for gcn
#define JR (NN / KSP)   // 512 j per split

// ---------------- device scratch (no allocation allowed) ----------------
__device__ __align__(256) unsigned g_A[(long)NN * NP];          // 2-bit packed adj (16 MB)
__device__ __align__(256) __nv_bfloat16 g_H[3L * NN * CH];      // H bf16 [plane][j][c]
__device__ float g_P[(long)KSP * NN * CH];                      // k-split fp32 partials (16 MB)
__device__ float g_pool[256 * CH];                              // per-block pooling partials

// ---------------------------------------------------------------------------
// repack: adj int32 -> 2-bit packed. One u32 per thread (16 entries).
// ---------------------------------------------------------------------------
__global__ __launch_bounds__(256) void repack_kernel(const int* __restrict__ adj) {
    const long idx = (long)blockIdx.x * 256 + threadIdx.x;      // 0 .. 4M-1
    const int4* src = (const int4*)(adj + idx * 16);
    unsigned w = 0;
#pragma unroll
    for (int q = 0; q < 4; q++) {
        int4 a = src[q];
        unsigned b = (unsigned)(a.x & 3) | ((unsigned)(a.y & 3) << 2) |
                     ((unsigned)(a.z & 3) << 4) | ((unsigned)(a.w & 3) << 6);
        w |= b << (q * 8);
    }
    g_A[idx] = w;
}

// ---------------------------------------------------------------------------
// hgen: H_k = Z @ w_k (bf16, [plane][j][c]).
// layer 0: Z = V.  layer 1: Z = relu(gb0 + sum_s P[s]).
// grid 256 x 256 threads (32 rows/block).
// ---------------------------------------------------------------------------
__global__ __launch_bounds__(256) void hgen_kernel(const float* __restrict__ V,
                                                   const float* __restrict__ bias,
                                                   const float* __restrict__ w1,
                                                   const float* __restrict__ w2,
                                                   const float* __restrict__ w3,
                                                   int layer) {
    __shared__ float sw[3][32][32];
    __shared__ float sZ[32][33];
    const int tid = threadIdx.x;
#pragma unroll
    for (int q = 0; q < 4; q++) {
        int id = tid + q * 256;
        sw[0][id >> 5][id & 31] = w1[id];
        sw[1][id >> 5][id & 31] = w2[id];
        sw[2][id >> 5][id & 31] = w3[id];
    }
    const int c = tid & 31, w = tid >> 5;
    const int j0 = blockIdx.x * 32;
#pragma unroll
    for (int rr = 0; rr < 4; rr++) {
        const int lr = w * 4 + rr, row = j0 + lr;
        float z;
        if (!layer) {
            z = V[(long)row * CH + c];
        } else {
            float s = 0.f;
#pragma unroll
            for (int p = 0; p < KSP; p++) s += g_P[((long)p * NN + row) * CH + c];
            z = fmaxf(bias[c] + s, 0.f);
        }
        sZ[lr][c] = z;
    }
    __syncthreads();
#pragma unroll
    for (int rr = 0; rr < 4; rr++) {
        const int lr = w * 4 + rr;
        const long row = j0 + lr;
        float a0 = 0.f, a1 = 0.f, a2 = 0.f;
#pragma unroll
        for (int d = 0; d < 32; d++) {
            float zd = sZ[lr][d];
            a0 += zd * sw[0][d][c];
            a1 += zd * sw[1][d][c];
            a2 += zd * sw[2][d][c];
        }
        g_H[(0L * NN + row) * CH + c] = __float2bfloat16(a0);
        g_H[(1L * NN + row) * CH + c] = __float2bfloat16(a1);
        g_H[(2L * NN + row) * CH + c] = __float2bfloat16(a2);
    }
}

// ---------------------------------------------------------------------------
// gcn: masked matmul from packed adj + bf16 H. grid (64 m-tiles, KSP), 256 thr.
// Verified R6 mainloop: nibble-extract + PRMT-LUT mask A-fragments, H via
// ldmatrix.x4.trans from smem superblock, HMMA m16n8k16 bf16 -> fp32.
// ---------------------------------------------------------------------------
__device__ __forceinline__ void mma_bf16(float* c, const unsigned* a,
                                         unsigned b0, unsigned b1) {
    asm volatile(
        "mma.sync.aligned.m16n8k16.row.col.f32.bf16.bf16.f32 "
        "{%0,%1,%2,%3},{%4,%5,%6,%7},{%8,%9},{%0,%1,%2,%3};"
        : "+f"(c[0]), "+f"(c[1]), "+f"(c[2]), "+f"(c[3])
        : "r"(a[0]), "r"(a[1]), "r"(a[2]), "r"(a[3]), "r"(b0), "r"(b1));
}

__device__ __forceinline__ void ldmx4t(unsigned& d0, unsigned& d1,
                                       unsigned& d2, unsigned& d3, unsigned addr) {
    asm volatile(
        "ldmatrix.sync.aligned.m8n8.x4.trans.shared.b16 {%0,%1,%2,%3}, [%4];"
        : "=r"(d0), "=r"(d1), "=r"(d2), "=r"(d3)
        : "r"(addr));
}

__global__ __launch_bounds__(256) void gcn_kernel() {
    __shared__ __align__(16) __nv_bfloat16 s_H[3 * 128 * 40];  // 3 planes x 128 j x 32 c (pad 40)

    const int tid = threadIdx.x;
    const int warp = tid >> 5, lane = tid & 31;
    const int g = lane >> 2, t = lane & 3;
    const int i0 = blockIdx.x * 128;
    const int ksp = blockIdx.y;
    const long jbase = (long)ksp * JR;

    float acc[16];
#pragma unroll
    for (int x = 0; x < 16; x++) acc[x] = 0.f;

    const unsigned sH_base = (unsigned)__cvta_generic_to_shared(s_H);
    const unsigned lm_row = lane & 15;
    const unsigned lm_col = (lane >> 4) * 8;
    const int r0 = i0 + warp * 16 + g;
    const unsigned* ap0 = g_A + (long)r0 * NP + (jbase >> 4);  // row g
    const unsigned* ap1 = ap0 + 8L * NP;                       // row g+8

    for (int jsb = 0; jsb < JR; jsb += 128) {
        __syncthreads();
        // stage H superblock: 3 planes x 128 j x 32 c bf16 = 24 KB
#pragma unroll
        for (int q = 0; q < 6; q++) {
            int id = tid + q * 256;
            int plane = id >> 9;
            int rem = id & 511;
            int row = rem >> 2, c4 = rem & 3;
            const __nv_bfloat16* src =
                g_H + ((long)plane * NN + jbase + jsb + row) * CH + c4 * 8;
            *(uint4*)(s_H + (plane * 128 + row) * 40 + c4 * 8) = *(const uint4*)src;
        }
        __syncthreads();

#pragma unroll
        for (int jo = 0; jo < 128; jo += 32) {
            const int jc = jsb + jo;
            const uint2 wg = *(const uint2*)(ap0 + (jc >> 4));   // row g,   32 cols
            const uint2 wh = *(const uint2*)(ap1 + (jc >> 4));   // row g+8, 32 cols
#pragma unroll
            for (int ks = 0; ks < 2; ks++) {
                const unsigned pg = ks ? wg.y : wg.x;
                const unsigned ph = ks ? wh.y : wh.x;
                unsigned e0 = (pg >> (4 * t)) & 0xFu;        // row g,   low cols
                unsigned e1 = (ph >> (4 * t)) & 0xFu;        // row g+8, low cols
                unsigned e2 = (pg >> (16 + 4 * t)) & 0xFu;   // row g,   high cols
                unsigned e3 = (ph >> (16 + 4 * t)) & 0xFu;   // row g+8, high cols

                unsigned A1[4], A2[4], A3[4];
#define MK(E, i)                                                              \
                {                                                             \
                    unsigned sel = ((E) & 3u) * 0x11u + ((E) >> 2) * 0x1100u + 0x4040u; \
                    A1[i] = __byte_perm(0x00008000u, 0x00003F00u, sel);       \
                    A2[i] = __byte_perm(0x00800000u, 0x003F0000u, sel);       \
                    A3[i] = __byte_perm(0x80000000u, 0x3F000000u, sel);       \
                }
                MK(e0, 0) MK(e1, 1) MK(e2, 2) MK(e3, 3)
#undef MK

#pragma unroll
                for (int m = 0; m < 3; m++) {
                    const unsigned* Am = (m == 0) ? A1 : ((m == 1) ? A2 : A3);
                    unsigned base = sH_base +
                        (((unsigned)(m * 128 + jo) + ks * 16 + lm_row) * 40 + lm_col) * 2;
                    unsigned b0, b1, b2, b3;
                    ldmx4t(b0, b1, b2, b3, base);          // n 0..15
                    mma_bf16(acc + 0, Am, b0, b1);
                    mma_bf16(acc + 4, Am, b2, b3);
                    ldmx4t(b0, b1, b2, b3, base + 32);     // n 16..31
                    mma_bf16(acc + 8, Am, b0, b1);
                    mma_bf16(acc + 12, Am, b2, b3);
                }
            }
        }
    }

    // fp32 partials (deterministic; reduced downstream)
    float* P = g_P + ((long)ksp * NN + i0 + warp * 16) * CH;
#pragma unroll
    for (int nt = 0; nt < 4; nt++) {
        int c = nt * 8 + 2 * t;
        *(float2*)(P + (g)     * CH + c) = make_float2(acc[nt * 4 + 0], acc[nt * 4 + 1]);
        *(float2*)(P + (g + 8) * CH + c) = make_float2(acc[nt * 4 + 2], acc[nt * 4 + 3]);
    }
}

// ---------------------------------------------------------------------------
// finish2: pooled sums of relu(gb1 + sum_s P[s]). grid 256 x 256.
// ---------------------------------------------------------------------------
__global__ __launch_bounds__(256) void finish2_kernel(const float* __restrict__ bias) {
    __shared__ float sred[8][32];
    const int c = threadIdx.x & 31, w = threadIdx.x >> 5;
    const int j0 = blockIdx.x * 32;
    const float b = bias[c];
    float local = 0.f;
#pragma unroll
    for (int rr = 0; rr < 4; rr++) {
        const int row = j0 + w * 4 + rr;
        float s = 0.f;
#pragma unroll
        for (int p = 0; p < KSP; p++) s += g_P[((long)p * NN + row) * CH + c];
        local += fmaxf(b + s, 0.f);
    }
    sred[w][c] = local;
    __syncthreads();
    if (w == 0) {
        float tt = sred[0][c];
#pragma unroll
        for (int q = 1; q < 8; q++) tt += sred[q][c];
        g_pool[blockIdx.x * 32 + c] = tt;
    }
}

// ---------------------------------------------------------------------------
// final: pool -> fc0(relu) -> fc1 -> sigmoid. 1 block, 256 threads.
// ---------------------------------------------------------------------------
__global__ void final_kernel(const float* __restrict__ fcW0, const float* __restrict__ fcb0,
                             const float* __restrict__ fcW1, const float* __restrict__ fcb1,
                             float* __restrict__ out) {
    __shared__ float sred[8][32];
    __shared__ float pool[32];
    const int c = threadIdx.x & 31, w = threadIdx.x >> 5;
    float s = 0.f;
    for (int i = 0; i < 32; i++) s += g_pool[(w * 32 + i) * 32 + c];
    sred[w][c] = s;
    __syncthreads();
    if (w == 0) {
        float p = sred[0][c];
#pragma unroll
        for (int q = 1; q < 8; q++) p += sred[q][c];
        pool[c] = p;
        __syncwarp();
        float o = fcb0[c];
#pragma unroll
        for (int d = 0; d < 32; d++) o += pool[d] * fcW0[c * 32 + d];
        o = fmaxf(o, 0.f);
        float v = o * fcW1[c];
#pragma unroll
        for (int off = 16; off; off >>= 1) v += __shfl_xor_sync(0xffffffffu, v, off);
        if (c == 0) out[0] = 1.f / (1.f + expf(-(v + fcb1[0])));
    }
}

// ---------------------------------------------------------------------------
extern "C" void kernel_launch(void* const* d_in, const int* in_sizes, int n_in,
                              void* d_out, int out_size) {
    (void)in_sizes; (void)n_in; (void)out_size;
    const float* V    = (const float*)d_in[0];
    const int*   adj  = (const int*)d_in[1];
    const float* w1_0 = (const float*)d_in[2];
    const float* w2_0 = (const float*)d_in[3];
    const float* w3_0 = (const float*)d_in[4];
    const float* gb_0 = (const float*)d_in[5];
    const float* w1_1 = (const float*)d_in[6];
    const float* w2_1 = (const float*)d_in[7];
    const float* w3_1 = (const float*)d_in[8];
    const float* gb_1 = (const float*)d_in[9];
    const float* fcW0 = (const float*)d_in[10];
    const float* fcb0 = (const float*)d_in[11];
    const float* fcW1 = (const float*)d_in[12];
    const float* fcb1 = (const float*)d_in[13];

    dim3 gG(64, KSP);

    repack_kernel<<<NN * NP / 256, 256>>>(adj);               // adj -> 2-bit packed
    hgen_kernel<<<256, 256>>>(V, gb_0, w1_0, w2_0, w3_0, 0);  // H planes (layer 1)
    gcn_kernel<<<gG, 256>>>();                                // layer-1 masked matmul
    hgen_kernel<<<256, 256>>>(V, gb_0, w1_1, w2_1, w3_1, 1);  // Z=relu(..), H planes (layer 2)
    gcn_kernel<<<gG, 256>>>();                                // layer-2 masked matmul
    finish2_kernel<<<256, 256>>>(gb_1);                       // relu+bias+pool partials
    final_kernel<<<1, 256>>>(fcW0, fcb0, fcW1, fcb1, (float*)d_out);
}